// round 12
// baseline (speedup 1.0000x reference)
#include <cuda_runtime.h>
#include <cuda_fp16.h>
#include <math.h>
#include <stdint.h>

// Problem sizes (fixed by the reference)
#define BB 64      // batch
#define TT 32      // timesteps
#define EE 512     // embed dim
#define HH 512     // hidden
#define H4 2048    // 4*H
#define VV 10000   // vocab
#define KP 1536    // augmented K' = 3*512 (fp16 split folded into K)

// ---------------- scratch (device globals: allocation-free) ----------------
__device__ __align__(16) float g_X[TT * BB * EE];        // [T][B][E]
__device__ __align__(16) float g_xproj[TT * BB * H4];    // [T][B][4H]
__device__ __align__(16) float g_hseq[TT * BB * HH];     // [T][B][H]
__device__ __align__(16) float g_h[BB * HH];
__device__ __align__(16) float g_c[BB * HH];
// fp16 split-augmented operands (A-side: hi,hi,lo; B-side: hi,lo,hi)
__device__ __align__(16) __half g_Xs[(size_t)H4 * KP];     // A' x_proj [2048][1536]
__device__ __align__(16) __half g_Hs[(size_t)H4 * KP];     // A' logits [2048][1536]
__device__ __align__(16) __half g_Wihs[(size_t)H4 * KP];   // B' W_ih
__device__ __align__(16) __half g_Fcs[(size_t)VV * KP];    // B' fc_W
__device__ int g_cap64;

// ---------------- captions dtype detection (int32 vs int64) ----------------
__global__ void detect_cap_kernel(const int* __restrict__ cap32) {
    if (threadIdx.x == 0 && blockIdx.x == 0) {
        int acc = 0;
        for (int i = 0; i < 256; i++) acc |= cap32[2 * i + 1];
        g_cap64 = (acc == 0) ? 1 : 0;
    }
}

// ---------------- build X: t=0 -> features, t>=1 -> embed(captions[:,t]) ----
__global__ void build_x_kernel(const float* __restrict__ feat,
                               const void* __restrict__ cap,
                               const float* __restrict__ embW) {
    int row = blockIdx.x;            // row = t*B + b
    int t = row >> 6;
    int b = row & 63;
    const float* src;
    if (t == 0) {
        src = feat + (size_t)b * EE;
    } else {
        long long idx;
        if (g_cap64) idx = ((const long long*)cap)[b * TT + t];
        else         idx = (long long)((const int*)cap)[b * TT + t];
        src = embW + (size_t)idx * EE;
    }
    float4* dst = (float4*)(g_X + (size_t)row * EE);
    const float4* s4 = (const float4*)src;
    for (int i = threadIdx.x; i < EE / 4; i += blockDim.x) dst[i] = s4[i];
}

// ---------------- fp16 split conversion (offline, K-augmented) -------------
// pat 0 (A-side): (hi, hi, lo);  pat 1 (B-side): (hi, lo, hi)
// sum over K' = Ah*Bh + Ah*Bl + Al*Bh. Residual ~2^-22 relative.
__global__ void conv_split_kernel(const float* __restrict__ src,
                                  __half* __restrict__ dst, int n, int pat) {
    int i = blockIdx.x * blockDim.x + threadIdx.x;
    if (i >= n) return;
    float x = src[i];
    __half hi = __float2half_rn(x);
    __half lo = __float2half_rn(x - __half2float(hi));
    size_t o = (size_t)i * 3;
    if (pat == 0) { dst[o] = hi; dst[o + 1] = hi; dst[o + 2] = lo; }
    else          { dst[o] = hi; dst[o + 1] = lo; dst[o + 2] = hi; }
}

// ---------------- PTX helpers ----------------------------------------------
__device__ __forceinline__ uint32_t smem_u32(const void* p) {
    uint32_t a;
    asm("{ .reg .u64 t; cvta.to.shared.u64 t, %1; cvt.u32.u64 %0, t; }"
        : "=r"(a) : "l"(p));
    return a;
}

__device__ __forceinline__ void cp16(uint32_t dst, const void* src, int valid) {
    // src-size register form: valid?16:0 -> OOB rows become zeros in smem.
    int sz = valid ? 16 : 0;
    asm volatile("cp.async.ca.shared.global [%0], [%1], 16, %2;"
                 :: "r"(dst), "l"(src), "r"(sz) : "memory");
}
__device__ __forceinline__ void cp_commit() {
    asm volatile("cp.async.commit_group;" ::: "memory");
}
template <int N>
__device__ __forceinline__ void cp_wait() {
    asm volatile("cp.async.wait_group %0;" :: "n"(N) : "memory");
}

__device__ __forceinline__ void ldsm_x4(uint32_t& r0, uint32_t& r1,
                                        uint32_t& r2, uint32_t& r3,
                                        uint32_t addr) {
    asm volatile("ldmatrix.sync.aligned.m8n8.x4.shared.b16 {%0,%1,%2,%3}, [%4];"
                 : "=r"(r0), "=r"(r1), "=r"(r2), "=r"(r3) : "r"(addr));
}

__device__ __forceinline__ void mma_f16(float* d, const uint32_t* a,
                                        const uint32_t* b) {
    asm volatile(
        "mma.sync.aligned.m16n8k16.row.col.f32.f16.f16.f32 "
        "{%0,%1,%2,%3}, {%4,%5,%6,%7}, {%8,%9}, {%0,%1,%2,%3};"
        : "+f"(d[0]), "+f"(d[1]), "+f"(d[2]), "+f"(d[3])
        : "r"(a[0]), "r"(a[1]), "r"(a[2]), "r"(a[3]), "r"(b[0]), "r"(b[1]));
}

// ---------------- fp16 HGEMM NT (ldmatrix + cp.async double buffer) --------
// C[M,N] = A'[M,KP] * B'[N,KP]^T (+bias1+bias2), halves in, fp32 out.
// mode 0: C[m*N+n]; mode 1: C[(b*TT+t)*N+n], m = t*64+b.
// 256 thr / 8 warps; block tile 128x128; warp tile 32x64 (2x8 m16n8k16);
// BK=64 halves. Smem rows padded to 72 halves = 144B (16B multiple; the 8
// ldmatrix row addresses hit 8 distinct 16B offsets mod 128B -> conflict-free).
#define GBK 64
#define ROWH 72                       // halves per padded smem row
#define ROWB (ROWH * 2)               // 144 bytes
#define AOFF 0
#define BOFF (128 * ROWB)             // 18432
#define BUFSZ (2 * 128 * ROWB)        // 36864 per buffer (A+B)
#define HG_SMEM (2 * BUFSZ)           // 73728 total (double buffered)
#define NCH (KP / GBK)                // 24 chunks

__global__ __launch_bounds__(256) void hgemm_nt_kernel(
    const __half* __restrict__ A, const __half* __restrict__ Bm,
    const float* __restrict__ bias1, const float* __restrict__ bias2,
    float* __restrict__ C, int M, int N, int mode)
{
    extern __shared__ char smem[];
    const uint32_t sb = smem_u32(smem);

    const int tid  = threadIdx.x;
    const int lane = tid & 31;
    const int warp = tid >> 5;
    const int wm   = (warp >> 1) * 32;   // 4 warps along M
    const int wn   = (warp & 1) * 64;    // 2 warps along N
    const int bm   = blockIdx.y * 128;
    const int bn   = blockIdx.x * 128;
    const int gid  = lane >> 2;          // 0..7
    const int tig  = lane & 3;           // 0..3

    // staging mapping: 1024 16B-chunks per matrix per buffer; 4 per thread.
    const int srow = tid >> 1;                  // wrong granularity? no:
    // idx = tid + 256*it, row = idx/8 (0..127), q = idx%8 (16B group)
    // ldmatrix address components (per thread, loop-invariant):
    const int lg = lane >> 3;            // 0..3 (matrix select)
    const int lr = lane & 7;             // 0..7 (row within matrix)
    (void)srow;

    float acc[2][8][4];
#pragma unroll
    for (int i = 0; i < 2; i++)
#pragma unroll
        for (int j = 0; j < 8; j++)
#pragma unroll
            for (int q = 0; q < 4; q++) acc[i][j][q] = 0.0f;

#define STAGE(buf, c)                                                          \
    do {                                                                       \
        const int koff = (c) * GBK;                                            \
        const uint32_t base = sb + (buf) * BUFSZ;                              \
        _Pragma("unroll")                                                      \
        for (int it = 0; it < 4; it++) {                                       \
            int idx = tid + it * 256;                                          \
            int row = idx >> 3;                                                \
            int q   = idx & 7;                                                 \
            cp16(base + AOFF + row * ROWB + q * 16,                            \
                 A + (size_t)(bm + row) * KP + koff + q * 8, 1);               \
            int nr = bn + row;                                                 \
            int ok = nr < N;                                                   \
            cp16(base + BOFF + row * ROWB + q * 16,                            \
                 Bm + (size_t)(ok ? nr : 0) * KP + koff + q * 8, ok);          \
        }                                                                      \
        cp_commit();                                                           \
    } while (0)

    STAGE(0, 0);

#pragma unroll 1
    for (int c = 0; c < NCH; c++) {
        const int buf = c & 1;
        if (c + 1 < NCH) {
            STAGE(buf ^ 1, c + 1);
            cp_wait<1>();          // chunk c resident (chunk c+1 may be inflight)
        } else {
            cp_wait<0>();
        }
        __syncthreads();

        const uint32_t abase = sb + buf * BUFSZ + AOFF;
        const uint32_t bbase = sb + buf * BUFSZ + BOFF;

#pragma unroll
        for (int ks = 0; ks < GBK; ks += 16) {
            // A frags: mat g -> row wm+i*16+(g&1)*8+lr, kcol ks+(g>>1)*8.
            // Register order matches R9's proven af[] mapping.
            uint32_t af[2][4];
#pragma unroll
            for (int i = 0; i < 2; i++) {
                uint32_t addr = abase +
                    (uint32_t)(wm + i * 16 + (lg & 1) * 8 + lr) * ROWB +
                    (uint32_t)(ks + (lg >> 1) * 8) * 2;
                ldsm_x4(af[i][0], af[i][1], af[i][2], af[i][3], addr);
            }
            // B frags: jp covers n8 tiles 2jp,2jp+1.
            // mat g -> row wn+jp*16+(g>>1)*8+lr, kcol ks+(g&1)*8.
            uint32_t bf[8][2];
#pragma unroll
            for (int jp = 0; jp < 4; jp++) {
                uint32_t addr = bbase +
                    (uint32_t)(wn + jp * 16 + (lg >> 1) * 8 + lr) * ROWB +
                    (uint32_t)(ks + (lg & 1) * 8) * 2;
                ldsm_x4(bf[2 * jp][0], bf[2 * jp][1],
                        bf[2 * jp + 1][0], bf[2 * jp + 1][1], addr);
            }
#pragma unroll
            for (int j = 0; j < 8; j++)
#pragma unroll
                for (int i = 0; i < 2; i++) mma_f16(acc[i][j], af[i], bf[j]);
        }
        __syncthreads();
    }

    // epilogue: c0=(gid,2tig), c1=(gid,2tig+1), c2/c3 = row+8 (as R9)
#pragma unroll
    for (int i = 0; i < 2; i++) {
#pragma unroll
        for (int j = 0; j < 8; j++) {
#pragma unroll
            for (int q = 0; q < 4; q++) {
                int m = bm + wm + i * 16 + gid + (q >= 2 ? 8 : 0);
                int n = bn + wn + j * 8 + tig * 2 + (q & 1);
                if (n < N) {
                    float v = acc[i][j][q];
                    if (bias1) v += bias1[n];
                    if (bias2) v += bias2[n];
                    if (mode == 0) {
                        C[(size_t)m * N + n] = v;
                    } else {
                        int t = m >> 6, b = m & 63;
                        C[(size_t)(b * TT + t) * N + n] = v;
                    }
                }
            }
        }
    }
#undef STAGE
}

// ---------------- fused LSTM step: matvec + gates + update, 1 kernel -------
__global__ __launch_bounds__(256) void lstm_step_kernel(
    const float* __restrict__ Whh, int t)
{
    const int u0 = blockIdx.x * 4;
    const int tid = threadIdx.x;
    const int tx = tid & 15;   // gate-row index r: g = tx>>2, j = tx&3
    const int ty = tid >> 4;   // batch quad

    __shared__ float hs[32][68];
    __shared__ float ws[32][20];
    __shared__ float gsm[16][68];

    float a0 = 0.f, a1 = 0.f, a2 = 0.f, a3 = 0.f;

    if (t > 0) {
        for (int k0 = 0; k0 < HH; k0 += 32) {
            for (int i = tid; i < 64 * 32; i += 256) {
                int b = i >> 5, kk = i & 31;
                hs[kk][b] = g_h[b * HH + k0 + kk];
            }
            for (int i = tid; i < 16 * 32; i += 256) {
                int r = i >> 5, kk = i & 31;
                int grow = (r >> 2) * HH + u0 + (r & 3);
                ws[kk][r] = Whh[(size_t)grow * HH + k0 + kk];
            }
            __syncthreads();
#pragma unroll
            for (int kk = 0; kk < 32; kk++) {
                float w = ws[kk][tx];
                float4 hv = *(const float4*)&hs[kk][ty * 4];
                a0 += hv.x * w;
                a1 += hv.y * w;
                a2 += hv.z * w;
                a3 += hv.w * w;
            }
            __syncthreads();
        }
    }

    gsm[tx][ty * 4 + 0] = a0;
    gsm[tx][ty * 4 + 1] = a1;
    gsm[tx][ty * 4 + 2] = a2;
    gsm[tx][ty * 4 + 3] = a3;
    __syncthreads();

    const int j = tid & 3;
    const int b = tid >> 2;
    const int u = u0 + j;

    const float* xp = g_xproj + ((size_t)(t * BB + b)) * H4;
    float gi = xp[u]           + gsm[0 * 4 + j][b];
    float gf = xp[HH + u]      + gsm[1 * 4 + j][b];
    float gg = xp[2 * HH + u]  + gsm[2 * 4 + j][b];
    float go = xp[3 * HH + u]  + gsm[3 * 4 + j][b];

    float i_g = 1.0f / (1.0f + expf(-gi));
    float f_g = 1.0f / (1.0f + expf(-gf));
    float g_g = tanhf(gg);
    float o_g = 1.0f / (1.0f + expf(-go));

    const int idx = b * HH + u;
    float c_old = (t > 0) ? g_c[idx] : 0.0f;
    float c = f_g * c_old + i_g * g_g;
    float h = o_g * tanhf(c);
    g_c[idx] = c;
    g_h[idx] = h;
    g_hseq[((size_t)(t * BB + b)) * HH + u] = h;
}

// ---------------- launch ----------------
extern "C" void kernel_launch(void* const* d_in, const int* in_sizes, int n_in,
                              void* d_out, int out_size)
{
    const float* features = (const float*)d_in[0];
    const void*  captions = d_in[1];                 // int32 or int64, detected
    const float* embed_W  = (const float*)d_in[2];
    const float* W_ih     = (const float*)d_in[3];
    const float* W_hh     = (const float*)d_in[4];
    const float* b_ih     = (const float*)d_in[5];
    const float* b_hh     = (const float*)d_in[6];
    const float* fc_W     = (const float*)d_in[7];
    const float* fc_b     = (const float*)d_in[8];
    float* out = (float*)d_out;

    // Resolve device-global scratch addresses + set smem attribute once
    // (host-side, allocation-free, graph-safe).
    static float *xproj_p = nullptr, *X_p = nullptr, *hseq_p = nullptr;
    static __half *Xs_p = nullptr, *Hs_p = nullptr, *Wihs_p = nullptr,
                  *Fcs_p = nullptr;
    if (!xproj_p) {
        void* p;
        cudaGetSymbolAddress(&p, g_xproj); xproj_p = (float*)p;
        cudaGetSymbolAddress(&p, g_X);     X_p     = (float*)p;
        cudaGetSymbolAddress(&p, g_hseq);  hseq_p  = (float*)p;
        cudaGetSymbolAddress(&p, g_Xs);    Xs_p    = (__half*)p;
        cudaGetSymbolAddress(&p, g_Hs);    Hs_p    = (__half*)p;
        cudaGetSymbolAddress(&p, g_Wihs);  Wihs_p  = (__half*)p;
        cudaGetSymbolAddress(&p, g_Fcs);   Fcs_p   = (__half*)p;
        cudaFuncSetAttribute(hgemm_nt_kernel,
                             cudaFuncAttributeMaxDynamicSharedMemorySize,
                             HG_SMEM);
    }

    detect_cap_kernel<<<1, 32>>>((const int*)captions);
    build_x_kernel<<<TT * BB, 128>>>(features, captions, embed_W);

    // offline fp16 split conversions
    conv_split_kernel<<<(H4 * EE + 255) / 256, 256>>>(X_p, Xs_p, H4 * EE, 0);
    conv_split_kernel<<<(H4 * EE + 255) / 256, 256>>>(W_ih, Wihs_p, H4 * EE, 1);
    conv_split_kernel<<<(VV * HH + 255) / 256, 256>>>(fc_W, Fcs_p, VV * HH, 1);

    // x_proj = X @ W_ih^T + b_ih + b_hh   [T*B, 4H]
    hgemm_nt_kernel<<<dim3(H4 / 128, (TT * BB) / 128), 256, HG_SMEM>>>(
        Xs_p, Wihs_p, b_ih, b_hh, xproj_p, TT * BB, H4, 0);

    // fused recurrence: one kernel per timestep
    for (int t = 0; t < TT; t++)
        lstm_step_kernel<<<128, 256>>>(W_hh, t);

    // convert h_seq, then logits GEMM
    conv_split_kernel<<<(H4 * HH + 255) / 256, 256>>>(hseq_p, Hs_p, H4 * HH, 0);
    hgemm_nt_kernel<<<dim3((VV + 127) / 128, (TT * BB) / 128), 256, HG_SMEM>>>(
        Hs_p, Fcs_p, fc_b, nullptr, out, TT * BB, VV, 1);
}